// round 2
// baseline (speedup 1.0000x reference)
#include <cuda_runtime.h>

#define NTHR 256
#define VPT  8                    // float4 per thread in the fast path
#define CHUNK (NTHR * VPT)        // float4 per block
#define MAXBLK 8192

// Scratch + completion counter (no allocation allowed in kernel_launch).
__device__ float        g_partials[MAXBLK];
__device__ unsigned int g_count = 0;

__device__ __forceinline__ float kl_elem(float p, float q) {
    // KL(p||q) = p*(log p - log q) + (1-p)*(log(1-p) - log(1-q))
    // Inputs bounded in [1e-4, 1-1e-4]; __logf rel err ~2^-21 << 1e-3 gate.
    float omp = 1.0f - p;
    float omq = 1.0f - q;
    float lp  = __logf(p);
    float lq  = __logf(q);
    float l1p = __logf(omp);
    float l1q = __logf(omq);
    return p * (lp - lq) + omp * (l1p - l1q);
}

__device__ __forceinline__ float block_reduce(float v) {
    #pragma unroll
    for (int o = 16; o > 0; o >>= 1)
        v += __shfl_down_sync(0xffffffffu, v, o);
    __shared__ float s[NTHR / 32];
    if ((threadIdx.x & 31) == 0) s[threadIdx.x >> 5] = v;
    __syncthreads();
    if (threadIdx.x < 32) {
        v = (threadIdx.x < NTHR / 32) ? s[threadIdx.x] : 0.0f;
        #pragma unroll
        for (int o = (NTHR / 64); o > 0; o >>= 1)
            v += __shfl_down_sync(0xffffffffu, v, o);
    }
    return v;   // valid in lane 0 of warp 0
}

__global__ void __launch_bounds__(NTHR)
kl_fused(const float* __restrict__ p, const float* __restrict__ q,
         int n, float* __restrict__ out) {
    const int nvec = n >> 2;
    const float4* __restrict__ p4 = reinterpret_cast<const float4*>(p);
    const float4* __restrict__ q4 = reinterpret_cast<const float4*>(q);

    float acc = 0.0f;
    const int base = blockIdx.x * CHUNK + threadIdx.x;

    if ((blockIdx.x + 1) * CHUNK <= nvec) {
        // Fast path: front-batch 16 LDG.128 (MLP-heavy), then compute.
        float4 a[VPT], b[VPT];
        #pragma unroll
        for (int k = 0; k < VPT; k++) a[k] = __ldcs(&p4[base + k * NTHR]);
        #pragma unroll
        for (int k = 0; k < VPT; k++) b[k] = __ldcs(&q4[base + k * NTHR]);
        #pragma unroll
        for (int k = 0; k < VPT; k++) {
            acc += kl_elem(a[k].x, b[k].x);
            acc += kl_elem(a[k].y, b[k].y);
            acc += kl_elem(a[k].z, b[k].z);
            acc += kl_elem(a[k].w, b[k].w);
        }
    } else {
        // Ragged last block: guarded loop over remaining float4s.
        for (int i = base; i < nvec; i += NTHR) {
            float4 a = __ldcs(&p4[i]);
            float4 b = __ldcs(&q4[i]);
            acc += kl_elem(a.x, b.x);
            acc += kl_elem(a.y, b.y);
            acc += kl_elem(a.z, b.z);
            acc += kl_elem(a.w, b.w);
        }
    }

    // Scalar tail (n % 4) handled by the last block.
    if (blockIdx.x == gridDim.x - 1) {
        for (int i = (nvec << 2) + threadIdx.x; i < n; i += NTHR)
            acc += kl_elem(p[i], q[i]);
    }

    float bsum = block_reduce(acc);
    __shared__ bool is_last;
    if (threadIdx.x == 0) {
        g_partials[blockIdx.x] = bsum;
        __threadfence();
        unsigned int done = atomicInc(&g_count, gridDim.x - 1);
        is_last = (done == gridDim.x - 1);
        // atomicInc wraps to 0 at gridDim.x-1 -> counter self-resets: deterministic replays.
    }
    __syncthreads();

    if (is_last) {
        // Deterministic final reduce: fixed-order read of all partials, fp64 accum.
        double dacc = 0.0;
        for (int i = threadIdx.x; i < gridDim.x; i += NTHR)
            dacc += (double)g_partials[i];

        __shared__ double sd[NTHR / 32];
        #pragma unroll
        for (int o = 16; o > 0; o >>= 1)
            dacc += __shfl_down_sync(0xffffffffu, dacc, o);
        if ((threadIdx.x & 31) == 0) sd[threadIdx.x >> 5] = dacc;
        __syncthreads();
        if (threadIdx.x == 0) {
            double t = 0.0;
            #pragma unroll
            for (int w = 0; w < NTHR / 32; w++) t += sd[w];
            out[0] = (float)t;
        }
    }
}

extern "C" void kernel_launch(void* const* d_in, const int* in_sizes, int n_in,
                              void* d_out, int out_size) {
    const float* p = (const float*)d_in[0];
    const float* q = (const float*)d_in[1];
    float* out = (float*)d_out;
    int n = in_sizes[0];

    int nvec = n >> 2;
    int blocks = (nvec + CHUNK - 1) / CHUNK;
    if (blocks < 1) blocks = 1;
    if (blocks > MAXBLK) blocks = MAXBLK;   // N=2^25 -> 4096 blocks; guard only
    // (grid-stride not needed: CHUNK*MAXBLK = 2^24 float4 = 2^26 floats >= N)

    kl_fused<<<blocks, NTHR>>>(p, q, n, out);
}

// round 3
// speedup vs baseline: 1.0396x; 1.0396x over previous
#include <cuda_runtime.h>

#define NTHR 256
#define NBLK 2048
#define VPT  2                      // float4 pairs per thread per iteration
#define ITER_CHUNK (NBLK * NTHR * VPT)   // float4 consumed per grid iteration

__device__ float        g_partials[NBLK];
__device__ unsigned int g_count = 0;

// Binary KL in log2 units; caller multiplies the SUM by ln2 once.
__device__ __forceinline__ float kl2_elem(float p, float q) {
    float omp = 1.0f - p;
    float omq = 1.0f - q;
    float lp  = __log2f(p);      // MUFU.LG2, no ln2 fixup
    float lq  = __log2f(q);
    float l1p = __log2f(omp);
    float l1q = __log2f(omq);
    return p * (lp - lq) + omp * (l1p - l1q);
}

__device__ __forceinline__ float kl2_vec4(float4 a, float4 b) {
    return kl2_elem(a.x, b.x) + kl2_elem(a.y, b.y)
         + kl2_elem(a.z, b.z) + kl2_elem(a.w, b.w);
}

__global__ void __launch_bounds__(NTHR)
kl_fused(const float* __restrict__ p, const float* __restrict__ q,
         int n, float* __restrict__ out) {
    const int nvec = n >> 2;
    const float4* __restrict__ p4 = reinterpret_cast<const float4*>(p);
    const float4* __restrict__ q4 = reinterpret_cast<const float4*>(q);

    float acc2 = 0.0f;   // accumulates in log2 units

    const int iters = nvec / ITER_CHUNK;           // full grid iterations
    int idx = blockIdx.x * (NTHR * VPT) + threadIdx.x;

    if (iters > 0) {
        // Software-pipelined main loop: prefetch next 4 LDG.128 before
        // computing the current 16 elements. Loads of iter k+1 overlap
        // the MUFU chain of iter k.
        float4 a0 = __ldcs(&p4[idx]);
        float4 a1 = __ldcs(&p4[idx + NTHR]);
        float4 b0 = __ldcs(&q4[idx]);
        float4 b1 = __ldcs(&q4[idx + NTHR]);

        for (int k = 1; k < iters; k++) {
            int nidx = idx + ITER_CHUNK;
            float4 na0 = __ldcs(&p4[nidx]);
            float4 na1 = __ldcs(&p4[nidx + NTHR]);
            float4 nb0 = __ldcs(&q4[nidx]);
            float4 nb1 = __ldcs(&q4[nidx + NTHR]);

            acc2 += kl2_vec4(a0, b0);
            acc2 += kl2_vec4(a1, b1);

            a0 = na0; a1 = na1; b0 = nb0; b1 = nb1;
            idx = nidx;
        }
        acc2 += kl2_vec4(a0, b0);
        acc2 += kl2_vec4(a1, b1);
        idx += ITER_CHUNK;
    }

    // Ragged remainder of float4s (none at N=2^25): plain grid-stride.
    for (int i = idx - threadIdx.x - blockIdx.x * (NTHR * VPT)  // = iters*ITER_CHUNK
               + blockIdx.x * NTHR + threadIdx.x;
         i < nvec; i += NBLK * NTHR) {
        acc2 += kl2_vec4(__ldcs(&p4[i]), __ldcs(&q4[i]));
    }

    // Scalar tail (n % 4) handled by the last block.
    if (blockIdx.x == gridDim.x - 1) {
        for (int i = (nvec << 2) + threadIdx.x; i < n; i += NTHR)
            acc2 += kl2_elem(p[i], q[i]);
    }

    // Convert log2 -> ln once per thread.
    float acc = acc2 * 0.6931471805599453f;

    // Block reduce
    #pragma unroll
    for (int o = 16; o > 0; o >>= 1)
        acc += __shfl_down_sync(0xffffffffu, acc, o);
    __shared__ float s[NTHR / 32];
    if ((threadIdx.x & 31) == 0) s[threadIdx.x >> 5] = acc;
    __syncthreads();
    float bsum = 0.0f;
    if (threadIdx.x < 32) {
        bsum = (threadIdx.x < NTHR / 32) ? s[threadIdx.x] : 0.0f;
        #pragma unroll
        for (int o = (NTHR / 64); o > 0; o >>= 1)
            bsum += __shfl_down_sync(0xffffffffu, bsum, o);
    }

    __shared__ bool is_last;
    if (threadIdx.x == 0) {
        g_partials[blockIdx.x] = bsum;
        __threadfence();
        // atomicInc wraps to 0 at gridDim.x-1 -> self-resetting, graph-replay safe.
        unsigned int done = atomicInc(&g_count, gridDim.x - 1);
        is_last = (done == gridDim.x - 1);
    }
    __syncthreads();

    if (is_last) {
        // Deterministic fixed-order final reduce in fp64.
        double dacc = 0.0;
        for (int i = threadIdx.x; i < gridDim.x; i += NTHR)
            dacc += (double)g_partials[i];
        #pragma unroll
        for (int o = 16; o > 0; o >>= 1)
            dacc += __shfl_down_sync(0xffffffffu, dacc, o);
        __shared__ double sd[NTHR / 32];
        if ((threadIdx.x & 31) == 0) sd[threadIdx.x >> 5] = dacc;
        __syncthreads();
        if (threadIdx.x == 0) {
            double t = 0.0;
            #pragma unroll
            for (int w = 0; w < NTHR / 32; w++) t += sd[w];
            out[0] = (float)t;
        }
    }
}

extern "C" void kernel_launch(void* const* d_in, const int* in_sizes, int n_in,
                              void* d_out, int out_size) {
    const float* p = (const float*)d_in[0];
    const float* q = (const float*)d_in[1];
    float* out = (float*)d_out;
    int n = in_sizes[0];

    kl_fused<<<NBLK, NTHR>>>(p, q, n, out);
}

// round 4
// speedup vs baseline: 1.0559x; 1.0157x over previous
#include <cuda_runtime.h>

#define NTHR 256
#define NBLK 2048
#define VPT  2                           // float4 pairs per thread per iteration
#define ITER_CHUNK (NBLK * NTHR * VPT)   // float4 consumed per grid iteration

__device__ float        g_partials[NBLK];
__device__ unsigned int g_count = 0;

// Raw MUFU.LG2 — inputs are guaranteed normal ([1e-4, 1-1e-4]), so the
// denormal fixup code in __log2f/__logf is dead weight. This is 1 instruction.
__device__ __forceinline__ float lg2_raw(float x) {
    float r;
    asm("lg2.approx.ftz.f32 %0, %1;" : "=f"(r) : "f"(x));
    return r;
}

// Binary KL in log2 units; the SUM is multiplied by ln2 once at the end.
__device__ __forceinline__ float kl2_elem(float p, float q) {
    float omp = 1.0f - p;
    float omq = 1.0f - q;
    float d1  = lg2_raw(p)   - lg2_raw(q);
    float d2  = lg2_raw(omp) - lg2_raw(omq);
    return fmaf(p, d1, omp * d2);
}

__device__ __forceinline__ float kl2_vec4(float4 a, float4 b) {
    return (kl2_elem(a.x, b.x) + kl2_elem(a.y, b.y))
         + (kl2_elem(a.z, b.z) + kl2_elem(a.w, b.w));
}

__global__ void __launch_bounds__(NTHR)
kl_fused(const float* __restrict__ p, const float* __restrict__ q,
         int n, float* __restrict__ out) {
    const int nvec = n >> 2;
    const float4* __restrict__ p4 = reinterpret_cast<const float4*>(p);
    const float4* __restrict__ q4 = reinterpret_cast<const float4*>(q);

    float acc2 = 0.0f;   // log2 units

    const int iters = nvec / ITER_CHUNK;
    int idx = blockIdx.x * (NTHR * VPT) + threadIdx.x;

    if (iters > 0) {
        // Software pipeline: next iteration's 4 LDG.128 issue before this
        // iteration's MUFU chain, so memory latency overlaps compute.
        float4 a0 = __ldcs(&p4[idx]);
        float4 a1 = __ldcs(&p4[idx + NTHR]);
        float4 b0 = __ldcs(&q4[idx]);
        float4 b1 = __ldcs(&q4[idx + NTHR]);

        for (int k = 1; k < iters; k++) {
            int nidx = idx + ITER_CHUNK;
            float4 na0 = __ldcs(&p4[nidx]);
            float4 na1 = __ldcs(&p4[nidx + NTHR]);
            float4 nb0 = __ldcs(&q4[nidx]);
            float4 nb1 = __ldcs(&q4[nidx + NTHR]);

            acc2 += kl2_vec4(a0, b0);
            acc2 += kl2_vec4(a1, b1);

            a0 = na0; a1 = na1; b0 = nb0; b1 = nb1;
            idx = nidx;
        }
        acc2 += kl2_vec4(a0, b0);
        acc2 += kl2_vec4(a1, b1);
        idx += ITER_CHUNK;
    }

    // Ragged remainder of float4s (none at N=2^25): plain grid-stride.
    {
        int rem_base = iters * ITER_CHUNK + blockIdx.x * NTHR + threadIdx.x;
        for (int i = rem_base; i < nvec; i += NBLK * NTHR)
            acc2 += kl2_vec4(__ldcs(&p4[i]), __ldcs(&q4[i]));
    }

    // Scalar tail (n % 4): last block only.
    if (blockIdx.x == gridDim.x - 1) {
        for (int i = (nvec << 2) + threadIdx.x; i < n; i += NTHR)
            acc2 += kl2_elem(p[i], q[i]);
    }

    float acc = acc2 * 0.6931471805599453f;   // log2 -> ln, once

    // Block reduce
    #pragma unroll
    for (int o = 16; o > 0; o >>= 1)
        acc += __shfl_down_sync(0xffffffffu, acc, o);
    __shared__ float s[NTHR / 32];
    if ((threadIdx.x & 31) == 0) s[threadIdx.x >> 5] = acc;
    __syncthreads();
    float bsum = 0.0f;
    if (threadIdx.x < 32) {
        bsum = (threadIdx.x < NTHR / 32) ? s[threadIdx.x] : 0.0f;
        #pragma unroll
        for (int o = (NTHR / 64); o > 0; o >>= 1)
            bsum += __shfl_down_sync(0xffffffffu, bsum, o);
    }

    __shared__ bool is_last;
    if (threadIdx.x == 0) {
        g_partials[blockIdx.x] = bsum;
        __threadfence();
        // atomicInc wraps to 0 at gridDim.x-1 -> self-resetting, graph-replay safe.
        unsigned int done = atomicInc(&g_count, gridDim.x - 1);
        is_last = (done == gridDim.x - 1);
    }
    __syncthreads();

    if (is_last) {
        // Deterministic fixed-order final reduce in fp64.
        double dacc = 0.0;
        for (int i = threadIdx.x; i < gridDim.x; i += NTHR)
            dacc += (double)g_partials[i];
        #pragma unroll
        for (int o = 16; o > 0; o >>= 1)
            dacc += __shfl_down_sync(0xffffffffu, dacc, o);
        __shared__ double sd[NTHR / 32];
        if ((threadIdx.x & 31) == 0) sd[threadIdx.x >> 5] = dacc;
        __syncthreads();
        if (threadIdx.x == 0) {
            double t = 0.0;
            #pragma unroll
            for (int w = 0; w < NTHR / 32; w++) t += sd[w];
            out[0] = (float)t;
        }
    }
}

extern "C" void kernel_launch(void* const* d_in, const int* in_sizes, int n_in,
                              void* d_out, int out_size) {
    const float* p = (const float*)d_in[0];
    const float* q = (const float*)d_in[1];
    float* out = (float*)d_out;
    int n = in_sizes[0];

    kl_fused<<<NBLK, NTHR>>>(p, q, n, out);
}

// round 5
// speedup vs baseline: 1.1290x; 1.0692x over previous
#include <cuda_runtime.h>

#define NTHR 256
#define NBLK 888                         // 6 blocks/SM x 148 SMs = exactly one wave
#define VPT  2                           // float4 pairs per thread per iteration
#define ITER_CHUNK (NBLK * NTHR * VPT)   // float4 consumed per grid iteration

__device__ float        g_partials[NBLK];
__device__ unsigned int g_count = 0;

// Raw MUFU.LG2 — inputs guaranteed in [1e-4, 1-1e-4] (always normal), so the
// denormal fixup in __log2f is dead weight. One instruction.
__device__ __forceinline__ float lg2_raw(float x) {
    float r;
    asm("lg2.approx.ftz.f32 %0, %1;" : "=f"(r) : "f"(x));
    return r;
}

// Binary KL in log2 units; the SUM is scaled by ln2 once at the end.
__device__ __forceinline__ float kl2_elem(float p, float q) {
    float omp = 1.0f - p;
    float omq = 1.0f - q;
    float d1  = lg2_raw(p)   - lg2_raw(q);
    float d2  = lg2_raw(omp) - lg2_raw(omq);
    return fmaf(p, d1, omp * d2);
}

__device__ __forceinline__ float kl2_vec4(float4 a, float4 b) {
    return (kl2_elem(a.x, b.x) + kl2_elem(a.y, b.y))
         + (kl2_elem(a.z, b.z) + kl2_elem(a.w, b.w));
}

__global__ void __launch_bounds__(NTHR, 6)
kl_fused(const float* __restrict__ p, const float* __restrict__ q,
         int n, float* __restrict__ out) {
    const int nvec = n >> 2;
    const float4* __restrict__ p4 = reinterpret_cast<const float4*>(p);
    const float4* __restrict__ q4 = reinterpret_cast<const float4*>(q);

    float acc2 = 0.0f;   // log2 units

    const int iters = nvec / ITER_CHUNK;   // identical for every block: balanced
    int idx = blockIdx.x * (NTHR * VPT) + threadIdx.x;

    if (iters > 0) {
        // Depth-1 software pipeline: next iteration's 4 LDG.128 are in flight
        // while this iteration's MUFU chain executes.
        float4 a0 = __ldcs(&p4[idx]);
        float4 a1 = __ldcs(&p4[idx + NTHR]);
        float4 b0 = __ldcs(&q4[idx]);
        float4 b1 = __ldcs(&q4[idx + NTHR]);

        for (int k = 1; k < iters; k++) {
            int nidx = idx + ITER_CHUNK;
            float4 na0 = __ldcs(&p4[nidx]);
            float4 na1 = __ldcs(&p4[nidx + NTHR]);
            float4 nb0 = __ldcs(&q4[nidx]);
            float4 nb1 = __ldcs(&q4[nidx + NTHR]);

            acc2 += kl2_vec4(a0, b0);
            acc2 += kl2_vec4(a1, b1);

            a0 = na0; a1 = na1; b0 = nb0; b1 = nb1;
            idx = nidx;
        }
        acc2 += kl2_vec4(a0, b0);
        acc2 += kl2_vec4(a1, b1);
    }

    // Remainder float4s (nvec % ITER_CHUNK): one grid-stride pass.
    {
        int rem_base = iters * ITER_CHUNK + blockIdx.x * NTHR + threadIdx.x;
        for (int i = rem_base; i < nvec; i += NBLK * NTHR)
            acc2 += kl2_vec4(__ldcs(&p4[i]), __ldcs(&q4[i]));
    }

    // Scalar tail (n % 4): last block only.
    if (blockIdx.x == gridDim.x - 1) {
        for (int i = (nvec << 2) + threadIdx.x; i < n; i += NTHR)
            acc2 += kl2_elem(p[i], q[i]);
    }

    float acc = acc2 * 0.6931471805599453f;   // log2 -> ln, once per thread

    // Block reduce
    #pragma unroll
    for (int o = 16; o > 0; o >>= 1)
        acc += __shfl_down_sync(0xffffffffu, acc, o);
    __shared__ float s[NTHR / 32];
    if ((threadIdx.x & 31) == 0) s[threadIdx.x >> 5] = acc;
    __syncthreads();
    float bsum = 0.0f;
    if (threadIdx.x < 32) {
        bsum = (threadIdx.x < NTHR / 32) ? s[threadIdx.x] : 0.0f;
        #pragma unroll
        for (int o = (NTHR / 64); o > 0; o >>= 1)
            bsum += __shfl_down_sync(0xffffffffu, bsum, o);
    }

    __shared__ bool is_last;
    if (threadIdx.x == 0) {
        g_partials[blockIdx.x] = bsum;
        __threadfence();
        // atomicInc wraps to 0 at gridDim.x-1 -> self-resetting, graph-replay safe.
        unsigned int done = atomicInc(&g_count, gridDim.x - 1);
        is_last = (done == gridDim.x - 1);
    }
    __syncthreads();

    if (is_last) {
        // Deterministic fixed-order final reduce in fp64.
        double dacc = 0.0;
        for (int i = threadIdx.x; i < gridDim.x; i += NTHR)
            dacc += (double)g_partials[i];
        #pragma unroll
        for (int o = 16; o > 0; o >>= 1)
            dacc += __shfl_down_sync(0xffffffffu, dacc, o);
        __shared__ double sd[NTHR / 32];
        if ((threadIdx.x & 31) == 0) sd[threadIdx.x >> 5] = dacc;
        __syncthreads();
        if (threadIdx.x == 0) {
            double t = 0.0;
            #pragma unroll
            for (int w = 0; w < NTHR / 32; w++) t += sd[w];
            out[0] = (float)t;
        }
    }
}

extern "C" void kernel_launch(void* const* d_in, const int* in_sizes, int n_in,
                              void* d_out, int out_size) {
    const float* p = (const float*)d_in[0];
    const float* q = (const float*)d_in[1];
    float* out = (float*)d_out;
    int n = in_sizes[0];

    kl_fused<<<NBLK, NTHR>>>(p, q, n, out);
}

// round 6
// speedup vs baseline: 1.1475x; 1.0164x over previous
#include <cuda_runtime.h>

#define NTHR 256
#define NBLK 888                         // 6 blocks/SM x 148 SMs = one full wave
#define VPT  2                           // float4 pairs per thread per iteration
#define ITER_CHUNK (NBLK * NTHR * VPT)   // float4 consumed per grid iteration

__device__ float        g_partials[NBLK];
__device__ unsigned int g_count = 0;

// Raw MUFU.LG2 — inputs guaranteed in [1e-4, 1-1e-4] (always normal).
__device__ __forceinline__ float lg2_raw(float x) {
    float r;
    asm("lg2.approx.ftz.f32 %0, %1;" : "=f"(r) : "f"(x));
    return r;
}

// FMA-pipe log2: exponent/mantissa split + degree-7 Horner (lg2 units).
// m in [sqrt(0.5), sqrt(2)), f = m-1 in [-0.2929, 0.4142].
// Taylor/ln2 coefficients; max abs err ~1.7e-4 (lg2 units) — well inside gate.
// Runs on ALU+FMA pipes, relieving the saturated MUFU pipe.
__device__ __forceinline__ float lg2_poly(float x) {
    int   xi = __float_as_int(x);
    int   k  = xi - 0x3f3504f3;          // center mantissa at sqrt(2)
    int   eb = k & 0xff800000;           // exponent bits (e << 23)
    float m  = __int_as_float(xi - eb);  // m in [0.70710678, 1.41421356)
    float e  = (float)(eb >> 23);
    float f  = m - 1.0f;
    float r  =            0.20609929f;   // 1/(7 ln2)
    r = fmaf(r, f, -0.24044917f);        // -1/(6 ln2)
    r = fmaf(r, f,  0.28853901f);        //  1/(5 ln2)
    r = fmaf(r, f, -0.36067376f);        // -1/(4 ln2)
    r = fmaf(r, f,  0.48089835f);        //  1/(3 ln2)
    r = fmaf(r, f, -0.72134752f);        // -1/(2 ln2)
    r = fmaf(r, f,  1.44269504f);        //  1/ln2
    return fmaf(r, f, e);
}

// Binary KL in log2 units, accumulated into two independent accumulators
// (two FMAs; no FMUL/FADD combine). 3 MUFU + 1 poly per element.
__device__ __forceinline__ void kl2_acc(float p, float q,
                                        float& accA, float& accB) {
    float omp = 1.0f - p;
    float omq = 1.0f - q;
    float d1  = lg2_raw(p)   - lg2_raw(q);
    float d2  = lg2_raw(omp) - lg2_poly(omq);
    accA = fmaf(p,   d1, accA);
    accB = fmaf(omp, d2, accB);
}

__device__ __forceinline__ void kl2_vec4(float4 a, float4 b,
                                         float& accA, float& accB) {
    kl2_acc(a.x, b.x, accA, accB);
    kl2_acc(a.y, b.y, accA, accB);
    kl2_acc(a.z, b.z, accA, accB);
    kl2_acc(a.w, b.w, accA, accB);
}

__global__ void __launch_bounds__(NTHR, 6)
kl_fused(const float* __restrict__ p, const float* __restrict__ q,
         int n, float* __restrict__ out) {
    const int nvec = n >> 2;
    const float4* __restrict__ p4 = reinterpret_cast<const float4*>(p);
    const float4* __restrict__ q4 = reinterpret_cast<const float4*>(q);

    float accA = 0.0f, accB = 0.0f;   // log2 units

    const int iters = nvec / ITER_CHUNK;   // identical for all blocks
    int idx = blockIdx.x * (NTHR * VPT) + threadIdx.x;

    if (iters > 0) {
        // Depth-1 software pipeline: next iteration's 4 LDG.128 in flight
        // while this iteration's MUFU/FMA chain executes.
        float4 a0 = __ldcs(&p4[idx]);
        float4 a1 = __ldcs(&p4[idx + NTHR]);
        float4 b0 = __ldcs(&q4[idx]);
        float4 b1 = __ldcs(&q4[idx + NTHR]);

        for (int k = 1; k < iters; k++) {
            int nidx = idx + ITER_CHUNK;
            float4 na0 = __ldcs(&p4[nidx]);
            float4 na1 = __ldcs(&p4[nidx + NTHR]);
            float4 nb0 = __ldcs(&q4[nidx]);
            float4 nb1 = __ldcs(&q4[nidx + NTHR]);

            kl2_vec4(a0, b0, accA, accB);
            kl2_vec4(a1, b1, accA, accB);

            a0 = na0; a1 = na1; b0 = nb0; b1 = nb1;
            idx = nidx;
        }
        kl2_vec4(a0, b0, accA, accB);
        kl2_vec4(a1, b1, accA, accB);
    }

    // Remainder float4s: one grid-stride pass.
    {
        int rem_base = iters * ITER_CHUNK + blockIdx.x * NTHR + threadIdx.x;
        for (int i = rem_base; i < nvec; i += NBLK * NTHR)
            kl2_vec4(__ldcs(&p4[i]), __ldcs(&q4[i]), accA, accB);
    }

    // Scalar tail (n % 4): last block only.
    if (blockIdx.x == gridDim.x - 1) {
        for (int i = (nvec << 2) + threadIdx.x; i < n; i += NTHR)
            kl2_acc(p[i], q[i], accA, accB);
    }

    float acc = (accA + accB) * 0.6931471805599453f;   // log2 -> ln, once

    // Block reduce
    #pragma unroll
    for (int o = 16; o > 0; o >>= 1)
        acc += __shfl_down_sync(0xffffffffu, acc, o);
    __shared__ float s[NTHR / 32];
    if ((threadIdx.x & 31) == 0) s[threadIdx.x >> 5] = acc;
    __syncthreads();
    float bsum = 0.0f;
    if (threadIdx.x < 32) {
        bsum = (threadIdx.x < NTHR / 32) ? s[threadIdx.x] : 0.0f;
        #pragma unroll
        for (int o = (NTHR / 64); o > 0; o >>= 1)
            bsum += __shfl_down_sync(0xffffffffu, bsum, o);
    }

    __shared__ bool is_last;
    if (threadIdx.x == 0) {
        g_partials[blockIdx.x] = bsum;
        __threadfence();
        // atomicInc wraps to 0 at gridDim.x-1 -> self-resetting, graph-replay safe.
        unsigned int done = atomicInc(&g_count, gridDim.x - 1);
        is_last = (done == gridDim.x - 1);
    }
    __syncthreads();

    if (is_last) {
        // Deterministic fixed-order final reduce in fp64.
        double dacc = 0.0;
        for (int i = threadIdx.x; i < gridDim.x; i += NTHR)
            dacc += (double)g_partials[i];
        #pragma unroll
        for (int o = 16; o > 0; o >>= 1)
            dacc += __shfl_down_sync(0xffffffffu, dacc, o);
        __shared__ double sd[NTHR / 32];
        if ((threadIdx.x & 31) == 0) sd[threadIdx.x >> 5] = dacc;
        __syncthreads();
        if (threadIdx.x == 0) {
            double t = 0.0;
            #pragma unroll
            for (int w = 0; w < NTHR / 32; w++) t += sd[w];
            out[0] = (float)t;
        }
    }
}

extern "C" void kernel_launch(void* const* d_in, const int* in_sizes, int n_in,
                              void* d_out, int out_size) {
    const float* p = (const float*)d_in[0];
    const float* q = (const float*)d_in[1];
    float* out = (float*)d_out;
    int n = in_sizes[0];

    kl_fused<<<NBLK, NTHR>>>(p, q, n, out);
}